// round 1
// baseline (speedup 1.0000x reference)
#include <cuda_runtime.h>
#include <math.h>

// Problem constants
#define Bsz 2
#define Sq  1024
#define Dm  1024
#define Hn  16
#define Dhd 64
#define Mrows (Bsz*Sq)                       // 2048
#define OUT_ELEMS  ((size_t)Bsz*Sq*Dm)       // 2097152
#define ATTN_ELEMS ((size_t)Bsz*Hn*Sq*Sq)    // 33554432

// Scratch (device globals: allocation-free per harness rules)
__device__ float g_Q [Mrows*Dm];
__device__ float g_K [Mrows*Dm];
__device__ float g_V [Mrows*Dm];
__device__ float g_av[Mrows*Dm];
__device__ float g_x1[Mrows*Dm];
__device__ float g_h1[Mrows*Dm];
__device__ float g_ff[Mrows*Dm];
__device__ float g_attn_fb[ATTN_ELEMS];      // fallback if harness doesn't want attn

// ---------------------------------------------------------------------------
// Block reductions (256 threads, 8 warps)
// ---------------------------------------------------------------------------
__device__ __forceinline__ float block_sum256(float v, float* sh) {
#pragma unroll
    for (int o = 16; o; o >>= 1) v += __shfl_xor_sync(0xffffffffu, v, o);
    __syncthreads();
    if ((threadIdx.x & 31) == 0) sh[threadIdx.x >> 5] = v;
    __syncthreads();
    if (threadIdx.x < 32) {
        float m = (threadIdx.x < 8) ? sh[threadIdx.x] : 0.f;
#pragma unroll
        for (int o = 4; o; o >>= 1) m += __shfl_xor_sync(0xffffffffu, m, o);
        if (threadIdx.x == 0) sh[0] = m;
    }
    __syncthreads();
    return sh[0];
}

__device__ __forceinline__ float block_max256(float v, float* sh) {
#pragma unroll
    for (int o = 16; o; o >>= 1) v = fmaxf(v, __shfl_xor_sync(0xffffffffu, v, o));
    __syncthreads();
    if ((threadIdx.x & 31) == 0) sh[threadIdx.x >> 5] = v;
    __syncthreads();
    if (threadIdx.x < 32) {
        float m = (threadIdx.x < 8) ? sh[threadIdx.x] : -INFINITY;
#pragma unroll
        for (int o = 4; o; o >>= 1) m = fmaxf(m, __shfl_xor_sync(0xffffffffu, m, o));
        if (threadIdx.x == 0) sh[0] = m;
    }
    __syncthreads();
    return sh[0];
}

// ---------------------------------------------------------------------------
// Dense NT GEMM: C[M,N] = A[M,K] * Bw[N,K]^T (torch Linear: x @ W.T)
// Tiles: 128x64x16, 256 threads, 8x4 per thread.
// epi: 0=none, 1=+bias, 2=+bias & relu
// ---------------------------------------------------------------------------
__global__ void __launch_bounds__(256) gemm_nt_kernel(
    const float* __restrict__ A, const float* __restrict__ Bw,
    const float* __restrict__ bias, float* __restrict__ C,
    int M, int N, int K, int epi)
{
    __shared__ float As[16][129];
    __shared__ float Bs[16][65];
    const int tid = threadIdx.x;
    const int tx = tid & 15;        // N dir
    const int ty = tid >> 4;        // M dir
    const int m0 = blockIdx.y * 128;
    const int n0 = blockIdx.x * 64;

    float acc[8][4];
#pragma unroll
    for (int i = 0; i < 8; i++)
#pragma unroll
        for (int j = 0; j < 4; j++) acc[i][j] = 0.f;

    const float* Ab = A + (size_t)m0 * K;
    const float* Bb = Bw + (size_t)n0 * K;

    for (int k0 = 0; k0 < K; k0 += 16) {
#pragma unroll
        for (int i = 0; i < 8; i++) {
            int idx = tid + i * 256;
            int m = idx >> 4, k = idx & 15;
            As[k][m] = Ab[(size_t)m * K + k0 + k];
        }
#pragma unroll
        for (int i = 0; i < 4; i++) {
            int idx = tid + i * 256;
            int n = idx >> 4, k = idx & 15;
            Bs[k][n] = Bb[(size_t)n * K + k0 + k];
        }
        __syncthreads();
#pragma unroll
        for (int kk = 0; kk < 16; kk++) {
            float a[8], b[4];
#pragma unroll
            for (int i = 0; i < 8; i++) a[i] = As[kk][ty * 8 + i];
#pragma unroll
            for (int j = 0; j < 4; j++) b[j] = Bs[kk][tx * 4 + j];
#pragma unroll
            for (int i = 0; i < 8; i++)
#pragma unroll
                for (int j = 0; j < 4; j++) acc[i][j] = fmaf(a[i], b[j], acc[i][j]);
        }
        __syncthreads();
    }

#pragma unroll
    for (int i = 0; i < 8; i++) {
        int row = m0 + ty * 8 + i;
#pragma unroll
        for (int j = 0; j < 4; j++) {
            int col = n0 + tx * 4 + j;
            float v = acc[i][j];
            if (epi >= 1) v += bias[col];
            if (epi == 2) v = fmaxf(v, 0.f);
            C[(size_t)row * N + col] = v;
        }
    }
}

// ---------------------------------------------------------------------------
// Scores: per (b,h), w[q,k] = dot(Q[b,q,h,:], K[b,k,h,:]); mask then *0.125
// Tiles 64x64, full K=64 in one shot. Writes raw masked/scaled logits to attn.
// ---------------------------------------------------------------------------
__global__ void __launch_bounds__(256) scores_kernel(
    const float* __restrict__ Q, const float* __restrict__ Km,
    const int* __restrict__ mask, float* __restrict__ attn)
{
    __shared__ float Qs[64][65];
    __shared__ float Ks[64][65];
    const int tid = threadIdx.x;
    const int tx = tid & 15, ty = tid >> 4;
    const int bh = blockIdx.z;
    const int b = bh >> 4, h = bh & 15;
    const int q0 = blockIdx.y * 64, n0 = blockIdx.x * 64;

    const size_t baseQ = ((size_t)(b * Sq + q0)) * Dm + h * Dhd;
    const size_t baseK = ((size_t)(b * Sq + n0)) * Dm + h * Dhd;
#pragma unroll
    for (int i = 0; i < 16; i++) {
        int idx = tid + i * 256;
        int r = idx >> 6, d = idx & 63;
        Qs[d][r] = Q [baseQ + (size_t)r * Dm + d];
        Ks[d][r] = Km[baseK + (size_t)r * Dm + d];
    }
    __syncthreads();

    float acc[4][4];
#pragma unroll
    for (int i = 0; i < 4; i++)
#pragma unroll
        for (int j = 0; j < 4; j++) acc[i][j] = 0.f;

#pragma unroll
    for (int kk = 0; kk < 64; kk++) {
        float a[4], bb[4];
#pragma unroll
        for (int i = 0; i < 4; i++) a[i]  = Qs[kk][ty * 4 + i];
#pragma unroll
        for (int j = 0; j < 4; j++) bb[j] = Ks[kk][tx * 4 + j];
#pragma unroll
        for (int i = 0; i < 4; i++)
#pragma unroll
            for (int j = 0; j < 4; j++) acc[i][j] = fmaf(a[i], bb[j], acc[i][j]);
    }

#pragma unroll
    for (int i = 0; i < 4; i++) {
        int qq = q0 + ty * 4 + i;
#pragma unroll
        for (int j = 0; j < 4; j++) {
            int kcol = n0 + tx * 4 + j;
            float v = acc[i][j];
            if (mask[b * Sq + kcol]) v = -1.0e12f;   // mask BEFORE scaling
            v *= 0.125f;                             // 1/sqrt(64)
            attn[(((size_t)bh) * Sq + qq) * Sq + kcol] = v;
        }
    }
}

// ---------------------------------------------------------------------------
// Row softmax in place (rows of length 1024). One block (256 thr) per row.
// ---------------------------------------------------------------------------
__global__ void __launch_bounds__(256) softmax_kernel(float* __restrict__ attn)
{
    __shared__ float sh[32];
    const size_t row = blockIdx.x;
    float* p = attn + row * (size_t)Sq;
    const int tid = threadIdx.x;

    float4 v = reinterpret_cast<float4*>(p)[tid];
    float mx = fmaxf(fmaxf(v.x, v.y), fmaxf(v.z, v.w));
    mx = block_max256(mx, sh);

    v.x = expf(v.x - mx); v.y = expf(v.y - mx);
    v.z = expf(v.z - mx); v.w = expf(v.w - mx);
    float s = v.x + v.y + v.z + v.w;
    s = block_sum256(s, sh);
    float inv = 1.f / s;
    v.x *= inv; v.y *= inv; v.z *= inv; v.w *= inv;
    reinterpret_cast<float4*>(p)[tid] = v;
}

// ---------------------------------------------------------------------------
// AV: per (b,h): av[q,d] = sum_k attn[q,k] * V[b,k,h,d]. Tiles 64x64x32.
// ---------------------------------------------------------------------------
__global__ void __launch_bounds__(256) av_kernel(
    const float* __restrict__ attn, const float* __restrict__ V,
    float* __restrict__ av)
{
    __shared__ float Ps[32][65];
    __shared__ float Vs[32][65];
    const int tid = threadIdx.x;
    const int tx = tid & 15, ty = tid >> 4;
    const int bh = blockIdx.z;
    const int b = bh >> 4, h = bh & 15;
    const int q0 = blockIdx.y * 64;

    float acc[4][4];
#pragma unroll
    for (int i = 0; i < 4; i++)
#pragma unroll
        for (int j = 0; j < 4; j++) acc[i][j] = 0.f;

    for (int kb = 0; kb < Sq; kb += 32) {
#pragma unroll
        for (int i = 0; i < 8; i++) {
            int idx = tid + i * 256;
            int q = idx >> 5, k = idx & 31;
            Ps[k][q] = attn[(((size_t)bh) * Sq + q0 + q) * Sq + kb + k];
        }
#pragma unroll
        for (int i = 0; i < 8; i++) {
            int idx = tid + i * 256;
            int kv = idx >> 6, d = idx & 63;
            Vs[kv][d] = V[((size_t)(b * Sq + kb + kv)) * Dm + h * Dhd + d];
        }
        __syncthreads();
#pragma unroll
        for (int kk = 0; kk < 32; kk++) {
            float a[4], bb[4];
#pragma unroll
            for (int i = 0; i < 4; i++) a[i]  = Ps[kk][ty * 4 + i];
#pragma unroll
            for (int j = 0; j < 4; j++) bb[j] = Vs[kk][tx * 4 + j];
#pragma unroll
            for (int i = 0; i < 4; i++)
#pragma unroll
                for (int j = 0; j < 4; j++) acc[i][j] = fmaf(a[i], bb[j], acc[i][j]);
        }
        __syncthreads();
    }

#pragma unroll
    for (int i = 0; i < 4; i++) {
        int q = q0 + ty * 4 + i;
#pragma unroll
        for (int j = 0; j < 4; j++) {
            int d = tx * 4 + j;
            av[((size_t)(b * Sq + q)) * Dm + h * Dhd + d] = acc[i][j];
        }
    }
}

// ---------------------------------------------------------------------------
// LayerNorm of (a + r), torch semantics: unbiased std (ddof=1), eps on std.
// One block (256 threads, float4 each) per row of 1024.
// ---------------------------------------------------------------------------
__global__ void __launch_bounds__(256) ln_kernel(
    const float* __restrict__ a, const float* __restrict__ r,
    const float* __restrict__ gamma, const float* __restrict__ beta,
    float* __restrict__ y)
{
    __shared__ float sh[32];
    const int row = blockIdx.x;
    const int tid = threadIdx.x;

    float4 v = reinterpret_cast<const float4*>(a + (size_t)row * Dm)[tid];
    float4 vr = reinterpret_cast<const float4*>(r + (size_t)row * Dm)[tid];
    v.x += vr.x; v.y += vr.y; v.z += vr.z; v.w += vr.w;

    float s = v.x + v.y + v.z + v.w;
    s = block_sum256(s, sh);
    float mean = s * (1.0f / Dm);

    float dx = v.x - mean, dy = v.y - mean, dz = v.z - mean, dw = v.w - mean;
    float s2 = dx * dx + dy * dy + dz * dz + dw * dw;
    s2 = block_sum256(s2, sh);
    float var = s2 * (1.0f / (Dm - 1));
    float inv = 1.0f / (sqrtf(var) + 1e-8f);

    float4 g = reinterpret_cast<const float4*>(gamma)[tid];
    float4 bb = reinterpret_cast<const float4*>(beta)[tid];
    float4 o;
    o.x = g.x * dx * inv + bb.x;
    o.y = g.y * dy * inv + bb.y;
    o.z = g.z * dz * inv + bb.z;
    o.w = g.w * dw * inv + bb.w;
    reinterpret_cast<float4*>(y + (size_t)row * Dm)[tid] = o;
}

// ---------------------------------------------------------------------------
// Launch
// ---------------------------------------------------------------------------
extern "C" void kernel_launch(void* const* d_in, const int* in_sizes, int n_in,
                              void* d_out, int out_size)
{
    const float* x      = (const float*)d_in[0];
    const int*   mask   = (const int*)  d_in[1];
    const float* Wq     = (const float*)d_in[2];
    const float* Wk     = (const float*)d_in[3];
    const float* Wv     = (const float*)d_in[4];
    const float* Wo     = (const float*)d_in[5];
    const float* W1     = (const float*)d_in[6];
    const float* b1     = (const float*)d_in[7];
    const float* W2     = (const float*)d_in[8];
    const float* b2     = (const float*)d_in[9];
    const float* gamma1 = (const float*)d_in[10];
    const float* beta1  = (const float*)d_in[11];
    const float* gamma2 = (const float*)d_in[12];
    const float* beta2  = (const float*)d_in[13];

    float* out = (float*)d_out;

    // Resolve scratch device-global addresses (query only; capture-safe).
    float *pQ, *pK, *pV, *pav, *px1, *ph1, *pff, *pattn_fb;
    cudaGetSymbolAddress((void**)&pQ,  g_Q);
    cudaGetSymbolAddress((void**)&pK,  g_K);
    cudaGetSymbolAddress((void**)&pV,  g_V);
    cudaGetSymbolAddress((void**)&pav, g_av);
    cudaGetSymbolAddress((void**)&px1, g_x1);
    cudaGetSymbolAddress((void**)&ph1, g_h1);
    cudaGetSymbolAddress((void**)&pff, g_ff);
    cudaGetSymbolAddress((void**)&pattn_fb, g_attn_fb);

    // Second output (attn) goes straight into d_out when the harness expects it.
    float* attn = ((size_t)out_size >= OUT_ELEMS + ATTN_ELEMS)
                  ? (out + OUT_ELEMS) : pattn_fb;

    dim3 blk(256);
    dim3 gGemm(Dm / 64, Mrows / 128);           // (16,16)

    // QKV projections
    gemm_nt_kernel<<<gGemm, blk>>>(x, Wq, nullptr, pQ, Mrows, Dm, Dm, 0);
    gemm_nt_kernel<<<gGemm, blk>>>(x, Wk, nullptr, pK, Mrows, Dm, Dm, 0);
    gemm_nt_kernel<<<gGemm, blk>>>(x, Wv, nullptr, pV, Mrows, Dm, Dm, 0);

    // Attention logits (masked + scaled) -> attn buffer
    dim3 gSc(Sq / 64, Sq / 64, Bsz * Hn);       // (16,16,32)
    scores_kernel<<<gSc, blk>>>(pQ, pK, mask, attn);

    // Row softmax in place
    softmax_kernel<<<(unsigned)(Bsz * Hn * Sq), blk>>>(attn);

    // attn @ V
    dim3 gAv(1, Sq / 64, Bsz * Hn);             // (1,16,32)
    av_kernel<<<gAv, blk>>>(attn, pV, pav);

    // Output projection, LN1
    gemm_nt_kernel<<<gGemm, blk>>>(pav, Wo, nullptr, pff, Mrows, Dm, Dm, 0);
    ln_kernel<<<Mrows, blk>>>(x, pff, gamma1, beta1, px1);

    // FFN
    gemm_nt_kernel<<<gGemm, blk>>>(px1, W1, b1, ph1, Mrows, Dm, Dm, 2); // bias+relu
    gemm_nt_kernel<<<gGemm, blk>>>(ph1, W2, b2, pff, Mrows, Dm, Dm, 1); // bias

    // LN2 -> out
    ln_kernel<<<Mrows, blk>>>(px1, pff, gamma2, beta2, out);
}

// round 3
// speedup vs baseline: 2.4161x; 2.4161x over previous
#include <cuda_runtime.h>
#include <cuda_bf16.h>
#include <math.h>
#include <stdint.h>

// Problem constants
#define Bsz 2
#define Sq  1024
#define Dm  1024
#define Hn  16
#define Dhd 64
#define Mrows (Bsz*Sq)                       // 2048
#define OUT_ELEMS  ((size_t)Bsz*Sq*Dm)
#define ATTN_ELEMS ((size_t)Bsz*Hn*Sq*Sq)

typedef __nv_bfloat16  bf16;
typedef __nv_bfloat162 bf162;

// ---------------------------------------------------------------------------
// Scratch (device globals; allocation-free)
// ---------------------------------------------------------------------------
__device__ __align__(16) float g_Q [Mrows*Dm];
__device__ __align__(16) float g_K [Mrows*Dm];
__device__ __align__(16) float g_V [Mrows*Dm];
__device__ __align__(16) float g_av[Mrows*Dm];
__device__ __align__(16) float g_x1[Mrows*Dm];
__device__ __align__(16) float g_h1[Mrows*Dm];
__device__ __align__(16) float g_ff[Mrows*Dm];
__device__ __align__(16) float g_attn_fb[ATTN_ELEMS];

__device__ __align__(16) bf16 g_xh [Mrows*Dm], g_xl [Mrows*Dm];
__device__ __align__(16) bf16 g_Qh [Mrows*Dm], g_Ql [Mrows*Dm];
__device__ __align__(16) bf16 g_Kh [Mrows*Dm], g_Kl [Mrows*Dm];
__device__ __align__(16) bf16 g_avh[Mrows*Dm], g_avl[Mrows*Dm];
__device__ __align__(16) bf16 g_x1h[Mrows*Dm], g_x1l[Mrows*Dm];
__device__ __align__(16) bf16 g_h1h[Mrows*Dm], g_h1l[Mrows*Dm];
__device__ __align__(16) bf16 g_Wh [6*Dm*Dm], g_Wl [6*Dm*Dm];
__device__ __align__(16) bf16 g_Vth[32*64*1024], g_Vtl[32*64*1024];
__device__ __align__(16) bf16 g_Ph [ATTN_ELEMS], g_Pl [ATTN_ELEMS];

// ---------------------------------------------------------------------------
// PTX helpers (sm_80-baseline: mma.sync + ldmatrix + cp.async)
// ---------------------------------------------------------------------------
__device__ __forceinline__ uint32_t smem_u32(const void* p) {
    uint32_t a;
    asm("{ .reg .u64 t; cvta.to.shared.u64 t, %1; cvt.u32.u64 %0, t; }"
        : "=r"(a) : "l"(p));
    return a;
}

__device__ __forceinline__ void ldmx4(uint32_t* r, uint32_t addr) {
    asm volatile("ldmatrix.sync.aligned.m8n8.x4.shared.b16 {%0,%1,%2,%3}, [%4];"
                 : "=r"(r[0]), "=r"(r[1]), "=r"(r[2]), "=r"(r[3]) : "r"(addr));
}

__device__ __forceinline__ void mma16816(float* d, const uint32_t* a, const uint32_t* b) {
    asm volatile(
        "mma.sync.aligned.m16n8k16.row.col.f32.bf16.bf16.f32 "
        "{%0,%1,%2,%3}, {%4,%5,%6,%7}, {%8,%9}, {%0,%1,%2,%3};"
        : "+f"(d[0]), "+f"(d[1]), "+f"(d[2]), "+f"(d[3])
        : "r"(a[0]), "r"(a[1]), "r"(a[2]), "r"(a[3]), "r"(b[0]), "r"(b[1]));
}

#define CPA16(dst, src)  asm volatile("cp.async.cg.shared.global [%0], [%1], 16;" :: "r"(dst), "l"(src))
#define CPA_COMMIT()     asm volatile("cp.async.commit_group;" ::: "memory")
#define CPA_WAIT1()      asm volatile("cp.async.wait_group 1;" ::: "memory")
#define CPA_WAIT0()      asm volatile("cp.async.wait_group 0;" ::: "memory")

// ---------------------------------------------------------------------------
// fp32 -> bf16 (hi, lo) split
// ---------------------------------------------------------------------------
__device__ __forceinline__ void split1(float x, bf16& h, bf16& l) {
    h = __float2bfloat16_rn(x);
    l = __float2bfloat16_rn(x - __bfloat162float(h));
}

__global__ void __launch_bounds__(256) split_kernel(
    const float* __restrict__ src, bf16* __restrict__ hi, bf16* __restrict__ lo, int n4)
{
    int i = blockIdx.x * 256 + threadIdx.x;
    if (i >= n4) return;
    float4 v = reinterpret_cast<const float4*>(src)[i];
    bf16 h0,h1,h2,h3,l0,l1,l2,l3;
    split1(v.x,h0,l0); split1(v.y,h1,l1); split1(v.z,h2,l2); split1(v.w,h3,l3);
    bf162* H = reinterpret_cast<bf162*>(hi);
    bf162* L = reinterpret_cast<bf162*>(lo);
    H[2*i]   = bf162{h0,h1}; H[2*i+1] = bf162{h2,h3};
    L[2*i]   = bf162{l0,l1}; L[2*i+1] = bf162{l2,l3};
}

// ---------------------------------------------------------------------------
// V transpose + split: V[b,k,h,d] (fp32) -> Vt[bh][d][k] (bf16 hi/lo)
// ---------------------------------------------------------------------------
__global__ void __launch_bounds__(256) vtrans_kernel(
    const float* __restrict__ V, bf16* __restrict__ Vth, bf16* __restrict__ Vtl)
{
    __shared__ float t[64][129];
    const int tid = threadIdx.x;
    const int bh = blockIdx.y, b = bh >> 4, h = bh & 15;
    const int k0 = blockIdx.x * 128;
#pragma unroll
    for (int i = 0; i < 32; i++) {
        int idx = tid + i * 256;
        int d = idx & 63, kl = idx >> 6;
        t[d][kl] = V[(size_t)(b * Sq + k0 + kl) * Dm + h * Dhd + d];
    }
    __syncthreads();
#pragma unroll
    for (int i = 0; i < 32; i++) {
        int idx = tid + i * 256;
        int kl = idx & 127, d = idx >> 7;
        bf16 hh, ll; split1(t[d][kl], hh, ll);
        size_t o = ((size_t)bh * 64 + d) * Sq + k0 + kl;
        Vth[o] = hh; Vtl[o] = ll;
    }
}

// ---------------------------------------------------------------------------
// Dense NT GEMM (mma.sync): C[M,N] = (Ah+Al)[M,K]*(Bh+Bl)[N,K]^T
// Block 128x128, 8 warps (4m x 2n), warp tile 32x64, K-stage 32, dbl-buffered.
// smem per stage: 4 matrices x (128 rows x 40 bf16, 80B stride) = 40960B.
// ---------------------------------------------------------------------------
#define DPAD 80            // bytes per smem row (40 bf16)
#define DMAT 10240         // bytes per 128x32 matrix
#define DSTAGE 40960

__global__ void __launch_bounds__(256, 1) gemm_mma(
    const bf16* __restrict__ Ah, const bf16* __restrict__ Al,
    const bf16* __restrict__ Bh, const bf16* __restrict__ Bl,
    const float* __restrict__ bias, float* __restrict__ C,
    int M, int N, int K, int epi)
{
    extern __shared__ __align__(16) char dsm[];
    const uint32_t s0 = smem_u32(dsm);
    const int tid = threadIdx.x, lane = tid & 31, warp = tid >> 5;
    const int wm = warp & 3, wn = warp >> 2;
    const int m0 = blockIdx.y * 128, n0 = blockIdx.x * 128;

    float acc[2][8][4];
#pragma unroll
    for (int a = 0; a < 2; a++)
#pragma unroll
        for (int b = 0; b < 8; b++)
#pragma unroll
            for (int c = 0; c < 4; c++) acc[a][b][c] = 0.f;

    const bf16* srcs[4] = { Ah + (size_t)m0 * K, Al + (size_t)m0 * K,
                            Bh + (size_t)n0 * K, Bl + (size_t)n0 * K };

    auto load_stage = [&](int s, int k0) {
        uint32_t base = s0 + s * DSTAGE;
        int row0 = tid >> 2, ch = tid & 3;
#pragma unroll
        for (int m = 0; m < 4; m++) {
#pragma unroll
            for (int i = 0; i < 2; i++) {
                int row = row0 + i * 64;
                uint32_t dst = base + m * DMAT + row * DPAD + ch * 16;
                CPA16(dst, srcs[m] + (size_t)row * K + k0 + ch * 8);
            }
        }
        CPA_COMMIT();
    };

    const int NS = K / 32;
    load_stage(0, 0);
    for (int s = 0; s < NS; s++) {
        if (s + 1 < NS) { load_stage((s + 1) & 1, (s + 1) * 32); CPA_WAIT1(); }
        else            { CPA_WAIT0(); }
        __syncthreads();
        uint32_t base = s0 + (s & 1) * DSTAGE;
#pragma unroll
        for (int ks = 0; ks < 2; ks++) {
            uint32_t a_hi[2][4], a_lo[2][4], b_hi[8][2], b_lo[8][2];
#pragma unroll
            for (int mt = 0; mt < 2; mt++) {
                uint32_t off = (uint32_t)((wm*32 + mt*16 + (lane & 15)) * DPAD
                                          + (ks*16 + (lane >> 4) * 8) * 2);
                ldmx4(a_hi[mt], base + off);
                ldmx4(a_lo[mt], base + DMAT + off);
            }
#pragma unroll
            for (int np = 0; np < 4; np++) {
                uint32_t off = (uint32_t)((wn*64 + np*16 + (lane & 7) + ((lane >> 4) & 1) * 8) * DPAD
                                          + (ks*16 + ((lane >> 3) & 1) * 8) * 2);
                uint32_t r[4];
                ldmx4(r, base + 2*DMAT + off);
                b_hi[np*2][0] = r[0]; b_hi[np*2][1] = r[1];
                b_hi[np*2+1][0] = r[2]; b_hi[np*2+1][1] = r[3];
                ldmx4(r, base + 3*DMAT + off);
                b_lo[np*2][0] = r[0]; b_lo[np*2][1] = r[1];
                b_lo[np*2+1][0] = r[2]; b_lo[np*2+1][1] = r[3];
            }
#pragma unroll
            for (int mt = 0; mt < 2; mt++)
#pragma unroll
                for (int nt = 0; nt < 8; nt++) {
                    mma16816(acc[mt][nt], a_hi[mt], b_hi[nt]);
                    mma16816(acc[mt][nt], a_hi[mt], b_lo[nt]);
                    mma16816(acc[mt][nt], a_lo[mt], b_hi[nt]);
                }
        }
        __syncthreads();
    }

#pragma unroll
    for (int mt = 0; mt < 2; mt++) {
        int r0 = m0 + wm*32 + mt*16 + (lane >> 2);
#pragma unroll
        for (int half = 0; half < 2; half++) {
            int row = r0 + half * 8;
            float* cr = C + (size_t)row * N;
#pragma unroll
            for (int nt = 0; nt < 8; nt++) {
                int col = n0 + wn*64 + nt*8 + (lane & 3) * 2;
                float v0 = acc[mt][nt][half*2+0], v1 = acc[mt][nt][half*2+1];
                if (epi >= 1) { v0 += bias[col]; v1 += bias[col+1]; }
                if (epi == 2) { v0 = fmaxf(v0, 0.f); v1 = fmaxf(v1, 0.f); }
                float2 o; o.x = v0; o.y = v1;
                *(float2*)(cr + col) = o;
            }
        }
    }
}

// ---------------------------------------------------------------------------
// Scores (mma.sync): per (b,h), 128q x 128k tile, K=64 single stage.
// smem: 4 matrices x (128 rows x 72 bf16, 144B stride) = 73728B.
// ---------------------------------------------------------------------------
#define SPAD 144
#define SMAT 18432

__global__ void __launch_bounds__(256, 1) scores_mma(
    const bf16* __restrict__ Qh, const bf16* __restrict__ Ql,
    const bf16* __restrict__ KMh, const bf16* __restrict__ KMl,
    const int* __restrict__ mask, float* __restrict__ attn)
{
    extern __shared__ __align__(16) char dsm[];
    const uint32_t s0 = smem_u32(dsm);
    const int tid = threadIdx.x, lane = tid & 31, warp = tid >> 5;
    const int wm = warp & 3, wn = warp >> 2;
    const int bh = blockIdx.z, b = bh >> 4, h = bh & 15;
    const int q0 = blockIdx.y * 128, n0 = blockIdx.x * 128;

    const bf16* srcs[4] = {
        Qh  + (size_t)(b * Sq + q0) * Dm + h * Dhd,
        Ql  + (size_t)(b * Sq + q0) * Dm + h * Dhd,
        KMh + (size_t)(b * Sq + n0) * Dm + h * Dhd,
        KMl + (size_t)(b * Sq + n0) * Dm + h * Dhd };

#pragma unroll
    for (int m = 0; m < 4; m++) {
#pragma unroll
        for (int i = 0; i < 4; i++) {
            int slot = tid + i * 256;
            int row = slot >> 3, ch = slot & 7;
            *(uint4*)(dsm + m * SMAT + row * SPAD + ch * 16) =
                *(const uint4*)(srcs[m] + (size_t)row * Dm + ch * 8);
        }
    }
    __syncthreads();

    float acc[2][8][4];
#pragma unroll
    for (int a = 0; a < 2; a++)
#pragma unroll
        for (int bb = 0; bb < 8; bb++)
#pragma unroll
            for (int c = 0; c < 4; c++) acc[a][bb][c] = 0.f;

#pragma unroll
    for (int ks = 0; ks < 4; ks++) {
        uint32_t a_hi[2][4], a_lo[2][4], b_hi[8][2], b_lo[8][2];
#pragma unroll
        for (int mt = 0; mt < 2; mt++) {
            uint32_t off = (uint32_t)((wm*32 + mt*16 + (lane & 15)) * SPAD
                                      + (ks*16 + (lane >> 4) * 8) * 2);
            ldmx4(a_hi[mt], s0 + off);
            ldmx4(a_lo[mt], s0 + SMAT + off);
        }
#pragma unroll
        for (int np = 0; np < 4; np++) {
            uint32_t off = (uint32_t)((wn*64 + np*16 + (lane & 7) + ((lane >> 4) & 1) * 8) * SPAD
                                      + (ks*16 + ((lane >> 3) & 1) * 8) * 2);
            uint32_t r[4];
            ldmx4(r, s0 + 2*SMAT + off);
            b_hi[np*2][0] = r[0]; b_hi[np*2][1] = r[1];
            b_hi[np*2+1][0] = r[2]; b_hi[np*2+1][1] = r[3];
            ldmx4(r, s0 + 3*SMAT + off);
            b_lo[np*2][0] = r[0]; b_lo[np*2][1] = r[1];
            b_lo[np*2+1][0] = r[2]; b_lo[np*2+1][1] = r[3];
        }
#pragma unroll
        for (int mt = 0; mt < 2; mt++)
#pragma unroll
            for (int nt = 0; nt < 8; nt++) {
                mma16816(acc[mt][nt], a_hi[mt], b_hi[nt]);
                mma16816(acc[mt][nt], a_hi[mt], b_lo[nt]);
                mma16816(acc[mt][nt], a_lo[mt], b_hi[nt]);
            }
    }

#pragma unroll
    for (int mt = 0; mt < 2; mt++) {
        int r0 = q0 + wm*32 + mt*16 + (lane >> 2);
#pragma unroll
        for (int half = 0; half < 2; half++) {
            int row = r0 + half * 8;
            float* ar = attn + ((size_t)bh * Sq + row) * Sq;
#pragma unroll
            for (int nt = 0; nt < 8; nt++) {
                int col = n0 + wn*64 + nt*8 + (lane & 3) * 2;
                float v0 = acc[mt][nt][half*2+0], v1 = acc[mt][nt][half*2+1];
                v0 = mask[b*Sq + col]     ? -1.25e11f : v0 * 0.125f;
                v1 = mask[b*Sq + col + 1] ? -1.25e11f : v1 * 0.125f;
                float2 o; o.x = v0; o.y = v1;
                *(float2*)(ar + col) = o;
            }
        }
    }
}

// ---------------------------------------------------------------------------
// AV (mma.sync): per (b,h), 128q x 64d tile, K=1024 in 32 stages of 32.
// Warp tile 32x32 (4m x 2n warps). smem per stage: P 2x10240 + Vt 2x5120 = 30720B.
// ---------------------------------------------------------------------------
#define AVSTAGE 30720

__global__ void __launch_bounds__(256, 1) av_mma(
    const bf16* __restrict__ Ph, const bf16* __restrict__ Pl,
    const bf16* __restrict__ Vth, const bf16* __restrict__ Vtl,
    float* __restrict__ av)
{
    extern __shared__ __align__(16) char dsm[];
    const uint32_t s0 = smem_u32(dsm);
    const int tid = threadIdx.x, lane = tid & 31, warp = tid >> 5;
    const int wm = warp & 3, wn = warp >> 2;
    const int bh = blockIdx.y, b = bh >> 4, h = bh & 15;
    const int q0 = blockIdx.x * 128;
    const bf16* pa_h = Ph + (size_t)bh * Sq * Sq + (size_t)q0 * Sq;
    const bf16* pa_l = Pl + (size_t)bh * Sq * Sq + (size_t)q0 * Sq;
    const bf16* pb_h = Vth + (size_t)bh * 64 * Sq;
    const bf16* pb_l = Vtl + (size_t)bh * 64 * Sq;

    float acc[2][4][4];
#pragma unroll
    for (int a = 0; a < 2; a++)
#pragma unroll
        for (int bb = 0; bb < 4; bb++)
#pragma unroll
            for (int c = 0; c < 4; c++) acc[a][bb][c] = 0.f;

    auto load_stage = [&](int s, int k0) {
        uint32_t base = s0 + s * AVSTAGE;
        int row0 = tid >> 2, ch = tid & 3;
#pragma unroll
        for (int i = 0; i < 2; i++) {
            int row = row0 + i * 64;
            CPA16(base + row * DPAD + ch * 16,          pa_h + (size_t)row * Sq + k0 + ch * 8);
            CPA16(base + DMAT + row * DPAD + ch * 16,   pa_l + (size_t)row * Sq + k0 + ch * 8);
        }
        CPA16(base + 2*DMAT + row0 * DPAD + ch * 16,        pb_h + (size_t)row0 * Sq + k0 + ch * 8);
        CPA16(base + 2*DMAT + 5120 + row0 * DPAD + ch * 16, pb_l + (size_t)row0 * Sq + k0 + ch * 8);
        CPA_COMMIT();
    };

    const int NS = Sq / 32;
    load_stage(0, 0);
    for (int s = 0; s < NS; s++) {
        if (s + 1 < NS) { load_stage((s + 1) & 1, (s + 1) * 32); CPA_WAIT1(); }
        else            { CPA_WAIT0(); }
        __syncthreads();
        uint32_t base = s0 + (s & 1) * AVSTAGE;
#pragma unroll
        for (int ks = 0; ks < 2; ks++) {
            uint32_t a_hi[2][4], a_lo[2][4], b_hi[4][2], b_lo[4][2];
#pragma unroll
            for (int mt = 0; mt < 2; mt++) {
                uint32_t off = (uint32_t)((wm*32 + mt*16 + (lane & 15)) * DPAD
                                          + (ks*16 + (lane >> 4) * 8) * 2);
                ldmx4(a_hi[mt], base + off);
                ldmx4(a_lo[mt], base + DMAT + off);
            }
#pragma unroll
            for (int np = 0; np < 2; np++) {
                uint32_t off = (uint32_t)((wn*32 + np*16 + (lane & 7) + ((lane >> 4) & 1) * 8) * DPAD
                                          + (ks*16 + ((lane >> 3) & 1) * 8) * 2);
                uint32_t r[4];
                ldmx4(r, base + 2*DMAT + off);
                b_hi[np*2][0] = r[0]; b_hi[np*2][1] = r[1];
                b_hi[np*2+1][0] = r[2]; b_hi[np*2+1][1] = r[3];
                ldmx4(r, base + 2*DMAT + 5120 + off);
                b_lo[np*2][0] = r[0]; b_lo[np*2][1] = r[1];
                b_lo[np*2+1][0] = r[2]; b_lo[np*2+1][1] = r[3];
            }
#pragma unroll
            for (int mt = 0; mt < 2; mt++)
#pragma unroll
                for (int nt = 0; nt < 4; nt++) {
                    mma16816(acc[mt][nt], a_hi[mt], b_hi[nt]);
                    mma16816(acc[mt][nt], a_hi[mt], b_lo[nt]);
                    mma16816(acc[mt][nt], a_lo[mt], b_hi[nt]);
                }
        }
        __syncthreads();
    }

#pragma unroll
    for (int mt = 0; mt < 2; mt++) {
        int r0 = q0 + wm*32 + mt*16 + (lane >> 2);
#pragma unroll
        for (int half = 0; half < 2; half++) {
            int row = r0 + half * 8;
            float* orow = av + (size_t)(b * Sq + row) * Dm + h * Dhd;
#pragma unroll
            for (int nt = 0; nt < 4; nt++) {
                int col = wn*32 + nt*8 + (lane & 3) * 2;
                float2 o; o.x = acc[mt][nt][half*2+0]; o.y = acc[mt][nt][half*2+1];
                *(float2*)(orow + col) = o;
            }
        }
    }
}

// ---------------------------------------------------------------------------
// Row softmax in place + bf16 split of probabilities. One block per row.
// ---------------------------------------------------------------------------
__global__ void __launch_bounds__(256) softmax_split_kernel(
    float* __restrict__ attn, bf16* __restrict__ Ph, bf16* __restrict__ Pl)
{
    __shared__ float sh[32];
    const size_t rowo = (size_t)blockIdx.x * Sq;
    float* p = attn + rowo;
    const int tid = threadIdx.x;

    float4 v = reinterpret_cast<float4*>(p)[tid];
    float mx = fmaxf(fmaxf(v.x, v.y), fmaxf(v.z, v.w));
#pragma unroll
    for (int o = 16; o; o >>= 1) mx = fmaxf(mx, __shfl_xor_sync(0xffffffffu, mx, o));
    if ((tid & 31) == 0) sh[tid >> 5] = mx;
    __syncthreads();
    if (tid < 32) {
        float m = (tid < 8) ? sh[tid] : -INFINITY;
#pragma unroll
        for (int o = 4; o; o >>= 1) m = fmaxf(m, __shfl_xor_sync(0xffffffffu, m, o));
        if (tid == 0) sh[0] = m;
    }
    __syncthreads();
    mx = sh[0];
    __syncthreads();

    v.x = __expf(v.x - mx); v.y = __expf(v.y - mx);
    v.z = __expf(v.z - mx); v.w = __expf(v.w - mx);
    float s = v.x + v.y + v.z + v.w;
#pragma unroll
    for (int o = 16; o; o >>= 1) s += __shfl_xor_sync(0xffffffffu, s, o);
    if ((tid & 31) == 0) sh[tid >> 5] = s;
    __syncthreads();
    if (tid < 32) {
        float m = (tid < 8) ? sh[tid] : 0.f;
#pragma unroll
        for (int o = 4; o; o >>= 1) m += __shfl_xor_sync(0xffffffffu, m, o);
        if (tid == 0) sh[0] = m;
    }
    __syncthreads();
    float inv = 1.f / sh[0];
    v.x *= inv; v.y *= inv; v.z *= inv; v.w *= inv;
    reinterpret_cast<float4*>(p)[tid] = v;

    bf16 h0,h1,h2,h3,l0,l1,l2,l3;
    split1(v.x,h0,l0); split1(v.y,h1,l1); split1(v.z,h2,l2); split1(v.w,h3,l3);
    bf162* H = reinterpret_cast<bf162*>(Ph + rowo);
    bf162* L = reinterpret_cast<bf162*>(Pl + rowo);
    H[2*tid]   = bf162{h0,h1}; H[2*tid+1] = bf162{h2,h3};
    L[2*tid]   = bf162{l0,l1}; L[2*tid+1] = bf162{l2,l3};
}

// ---------------------------------------------------------------------------
// LayerNorm(a + r), torch semantics (ddof=1, eps on std); optional bf16 split.
// ---------------------------------------------------------------------------
__global__ void __launch_bounds__(256) ln_kernel(
    const float* __restrict__ a, const float* __restrict__ r,
    const float* __restrict__ gamma, const float* __restrict__ beta,
    float* __restrict__ y, bf16* __restrict__ yh, bf16* __restrict__ yl)
{
    __shared__ float sh[32];
    const int row = blockIdx.x;
    const int tid = threadIdx.x;

    float4 v = reinterpret_cast<const float4*>(a + (size_t)row * Dm)[tid];
    float4 vr = reinterpret_cast<const float4*>(r + (size_t)row * Dm)[tid];
    v.x += vr.x; v.y += vr.y; v.z += vr.z; v.w += vr.w;

    float s = v.x + v.y + v.z + v.w;
#pragma unroll
    for (int o = 16; o; o >>= 1) s += __shfl_xor_sync(0xffffffffu, s, o);
    if ((tid & 31) == 0) sh[tid >> 5] = s;
    __syncthreads();
    if (tid < 32) {
        float m = (tid < 8) ? sh[tid] : 0.f;
#pragma unroll
        for (int o = 4; o; o >>= 1) m += __shfl_xor_sync(0xffffffffu, m, o);
        if (tid == 0) sh[0] = m;
    }
    __syncthreads();
    float mean = sh[0] * (1.0f / Dm);
    __syncthreads();

    float dx = v.x - mean, dy = v.y - mean, dz = v.z - mean, dw = v.w - mean;
    float s2 = dx*dx + dy*dy + dz*dz + dw*dw;
#pragma unroll
    for (int o = 16; o; o >>= 1) s2 += __shfl_xor_sync(0xffffffffu, s2, o);
    if ((tid & 31) == 0) sh[tid >> 5] = s2;
    __syncthreads();
    if (tid < 32) {
        float m = (tid < 8) ? sh[tid] : 0.f;
#pragma unroll
        for (int o = 4; o; o >>= 1) m += __shfl_xor_sync(0xffffffffu, m, o);
        if (tid == 0) sh[0] = m;
    }
    __syncthreads();
    float var = sh[0] * (1.0f / (Dm - 1));
    float inv = 1.0f / (sqrtf(var) + 1e-8f);

    float4 g = reinterpret_cast<const float4*>(gamma)[tid];
    float4 bb = reinterpret_cast<const float4*>(beta)[tid];
    float4 o;
    o.x = g.x * dx * inv + bb.x;
    o.y = g.y * dy * inv + bb.y;
    o.z = g.z * dz * inv + bb.z;
    o.w = g.w * dw * inv + bb.w;
    reinterpret_cast<float4*>(y + (size_t)row * Dm)[tid] = o;

    if (yh) {
        bf16 h0,h1,h2,h3,l0,l1,l2,l3;
        split1(o.x,h0,l0); split1(o.y,h1,l1); split1(o.z,h2,l2); split1(o.w,h3,l3);
        bf162* H = reinterpret_cast<bf162*>(yh + (size_t)row * Dm);
        bf162* L = reinterpret_cast<bf162*>(yl + (size_t)row * Dm);
        H[2*tid]   = bf162{h0,h1}; H[2*tid+1] = bf162{h2,h3};
        L[2*tid]   = bf162{l0,l1}; L[2*tid+1] = bf162{l2,l3};
    }
}

// ---------------------------------------------------------------------------
// Launch
// ---------------------------------------------------------------------------
extern "C" void kernel_launch(void* const* d_in, const int* in_sizes, int n_in,
                              void* d_out, int out_size)
{
    const float* x      = (const float*)d_in[0];
    const int*   mask   = (const int*)  d_in[1];
    const float* W[6]   = { (const float*)d_in[2], (const float*)d_in[3],
                            (const float*)d_in[4], (const float*)d_in[5],
                            (const float*)d_in[6], (const float*)d_in[8] };
    const float* b1     = (const float*)d_in[7];
    const float* b2     = (const float*)d_in[9];
    const float* gamma1 = (const float*)d_in[10];
    const float* beta1  = (const float*)d_in[11];
    const float* gamma2 = (const float*)d_in[12];
    const float* beta2  = (const float*)d_in[13];
    float* out = (float*)d_out;

    float *pQ,*pK,*pV,*pav,*px1,*ph1,*pff,*pattn_fb;
    cudaGetSymbolAddress((void**)&pQ, g_Q);   cudaGetSymbolAddress((void**)&pK, g_K);
    cudaGetSymbolAddress((void**)&pV, g_V);   cudaGetSymbolAddress((void**)&pav, g_av);
    cudaGetSymbolAddress((void**)&px1, g_x1); cudaGetSymbolAddress((void**)&ph1, g_h1);
    cudaGetSymbolAddress((void**)&pff, g_ff); cudaGetSymbolAddress((void**)&pattn_fb, g_attn_fb);
    bf16 *pxh,*pxl,*pQh,*pQl,*pKh,*pKl,*pavh,*pavl,*px1h,*px1l,*ph1h,*ph1l,*pWh,*pWl,*pVth,*pVtl,*pPh,*pPl;
    cudaGetSymbolAddress((void**)&pxh, g_xh);   cudaGetSymbolAddress((void**)&pxl, g_xl);
    cudaGetSymbolAddress((void**)&pQh, g_Qh);   cudaGetSymbolAddress((void**)&pQl, g_Ql);
    cudaGetSymbolAddress((void**)&pKh, g_Kh);   cudaGetSymbolAddress((void**)&pKl, g_Kl);
    cudaGetSymbolAddress((void**)&pavh, g_avh); cudaGetSymbolAddress((void**)&pavl, g_avl);
    cudaGetSymbolAddress((void**)&px1h, g_x1h); cudaGetSymbolAddress((void**)&px1l, g_x1l);
    cudaGetSymbolAddress((void**)&ph1h, g_h1h); cudaGetSymbolAddress((void**)&ph1l, g_h1l);
    cudaGetSymbolAddress((void**)&pWh, g_Wh);   cudaGetSymbolAddress((void**)&pWl, g_Wl);
    cudaGetSymbolAddress((void**)&pVth, g_Vth); cudaGetSymbolAddress((void**)&pVtl, g_Vtl);
    cudaGetSymbolAddress((void**)&pPh, g_Ph);   cudaGetSymbolAddress((void**)&pPl, g_Pl);

    float* attn = ((size_t)out_size >= OUT_ELEMS + ATTN_ELEMS) ? (out + OUT_ELEMS) : pattn_fb;

    const int GM_SMEM = 2 * DSTAGE;        // 81920
    const int SC_SMEM = 4 * SMAT;          // 73728
    const int AV_SMEM = 2 * AVSTAGE;       // 61440
    cudaFuncSetAttribute(gemm_mma,   cudaFuncAttributeMaxDynamicSharedMemorySize, GM_SMEM);
    cudaFuncSetAttribute(scores_mma, cudaFuncAttributeMaxDynamicSharedMemorySize, SC_SMEM);
    cudaFuncSetAttribute(av_mma,     cudaFuncAttributeMaxDynamicSharedMemorySize, AV_SMEM);

    dim3 blk(256);
    const int N4x = (Mrows * Dm) / 4;
    const int N4w = (Dm * Dm) / 4;
    dim3 gGemm(Dm / 128, Mrows / 128);     // (8, 16)

    // Splits: x + 6 weights
    split_kernel<<<N4x / 256, blk>>>(x, pxh, pxl, N4x);
    for (int w = 0; w < 6; w++)
        split_kernel<<<N4w / 256, blk>>>(W[w], pWh + (size_t)w * Dm * Dm,
                                         pWl + (size_t)w * Dm * Dm, N4w);

    // QKV projections
    gemm_mma<<<gGemm, blk, GM_SMEM>>>(pxh, pxl, pWh + 0*(size_t)Dm*Dm, pWl + 0*(size_t)Dm*Dm, nullptr, pQ, Mrows, Dm, Dm, 0);
    gemm_mma<<<gGemm, blk, GM_SMEM>>>(pxh, pxl, pWh + 1*(size_t)Dm*Dm, pWl + 1*(size_t)Dm*Dm, nullptr, pK, Mrows, Dm, Dm, 0);
    gemm_mma<<<gGemm, blk, GM_SMEM>>>(pxh, pxl, pWh + 2*(size_t)Dm*Dm, pWl + 2*(size_t)Dm*Dm, nullptr, pV, Mrows, Dm, Dm, 0);

    split_kernel<<<N4x / 256, blk>>>(pQ, pQh, pQl, N4x);
    split_kernel<<<N4x / 256, blk>>>(pK, pKh, pKl, N4x);
    vtrans_kernel<<<dim3(Sq / 128, 32), blk>>>(pV, pVth, pVtl);

    // Attention logits (masked+scaled) -> attn
    scores_mma<<<dim3(Sq / 128, Sq / 128, Bsz * Hn), blk, SC_SMEM>>>(pQh, pQl, pKh, pKl, mask, attn);

    // Softmax in place + P split
    softmax_split_kernel<<<(unsigned)(Bsz * Hn * Sq), blk>>>(attn, pPh, pPl);

    // attn @ V
    av_mma<<<dim3(Sq / 128, Bsz * Hn), blk, AV_SMEM>>>(pPh, pPl, pVth, pVtl, pav);

    // Output projection + LN1 (emits x1 split)
    split_kernel<<<N4x / 256, blk>>>(pav, pavh, pavl, N4x);
    gemm_mma<<<gGemm, blk, GM_SMEM>>>(pavh, pavl, pWh + 3*(size_t)Dm*Dm, pWl + 3*(size_t)Dm*Dm, nullptr, pff, Mrows, Dm, Dm, 0);
    ln_kernel<<<Mrows, blk>>>(x, pff, gamma1, beta1, px1, px1h, px1l);

    // FFN
    gemm_mma<<<gGemm, blk, GM_SMEM>>>(px1h, px1l, pWh + 4*(size_t)Dm*Dm, pWl + 4*(size_t)Dm*Dm, b1, ph1, Mrows, Dm, Dm, 2);
    split_kernel<<<N4x / 256, blk>>>(ph1, ph1h, ph1l, N4x);
    gemm_mma<<<gGemm, blk, GM_SMEM>>>(ph1h, ph1l, pWh + 5*(size_t)Dm*Dm, pWl + 5*(size_t)Dm*Dm, b2, pff, Mrows, Dm, Dm, 1);

    // LN2 -> out
    ln_kernel<<<Mrows, blk>>>(px1, pff, gamma2, beta2, out, nullptr, nullptr);
}

// round 4
// speedup vs baseline: 2.7719x; 1.1473x over previous
#include <cuda_runtime.h>
#include <cuda_fp16.h>
#include <math.h>
#include <stdint.h>

// Problem constants
#define Bsz 2
#define Sq  1024
#define Dm  1024
#define Hn  16
#define Dhd 64
#define Mrows (Bsz*Sq)                       // 2048
#define OUT_ELEMS  ((size_t)Bsz*Sq*Dm)
#define ATTN_ELEMS ((size_t)Bsz*Hn*Sq*Sq)

typedef __half  f16;
typedef __half2 f162;

// ---------------------------------------------------------------------------
// Scratch (device globals; allocation-free)
// ---------------------------------------------------------------------------
__device__ __align__(16) float g_V  [Mrows*Dm];
__device__ __align__(16) float g_x1 [Mrows*Dm];
__device__ __align__(16) float g_ff [Mrows*Dm];
__device__ __align__(16) float g_attn_fb[ATTN_ELEMS];

__device__ __align__(16) f16 g_xh [Mrows*Dm], g_xl [Mrows*Dm];
__device__ __align__(16) f16 g_Qh [Mrows*Dm], g_Ql [Mrows*Dm];
__device__ __align__(16) f16 g_Kh [Mrows*Dm], g_Kl [Mrows*Dm];
__device__ __align__(16) f16 g_avh[Mrows*Dm];
__device__ __align__(16) f16 g_x1h[Mrows*Dm];
__device__ __align__(16) f16 g_h1h[Mrows*Dm];
__device__ __align__(16) f16 g_Wh [6*Dm*Dm], g_Wl [6*Dm*Dm];
__device__ __align__(16) f16 g_Vth[32*64*1024], g_Vtl[32*64*1024];
__device__ __align__(16) f16 g_Ph [ATTN_ELEMS];

// ---------------------------------------------------------------------------
// PTX helpers (sm_80-baseline: mma.sync + ldmatrix + cp.async)
// ---------------------------------------------------------------------------
__device__ __forceinline__ uint32_t smem_u32(const void* p) {
    uint32_t a;
    asm("{ .reg .u64 t; cvta.to.shared.u64 t, %1; cvt.u32.u64 %0, t; }"
        : "=r"(a) : "l"(p));
    return a;
}

__device__ __forceinline__ void ldmx4(uint32_t* r, uint32_t addr) {
    asm volatile("ldmatrix.sync.aligned.m8n8.x4.shared.b16 {%0,%1,%2,%3}, [%4];"
                 : "=r"(r[0]), "=r"(r[1]), "=r"(r[2]), "=r"(r[3]) : "r"(addr));
}

__device__ __forceinline__ void mma16816(float* d, const uint32_t* a, const uint32_t* b) {
    asm volatile(
        "mma.sync.aligned.m16n8k16.row.col.f32.f16.f16.f32 "
        "{%0,%1,%2,%3}, {%4,%5,%6,%7}, {%8,%9}, {%0,%1,%2,%3};"
        : "+f"(d[0]), "+f"(d[1]), "+f"(d[2]), "+f"(d[3])
        : "r"(a[0]), "r"(a[1]), "r"(a[2]), "r"(a[3]), "r"(b[0]), "r"(b[1]));
}

#define CPA16(dst, src)  asm volatile("cp.async.cg.shared.global [%0], [%1], 16;" :: "r"(dst), "l"(src))
#define CPA_COMMIT()     asm volatile("cp.async.commit_group;" ::: "memory")
#define CPA_WAIT2()      asm volatile("cp.async.wait_group 2;" ::: "memory")

__device__ __forceinline__ void split1h(float x, f16& h, f16& l) {
    h = __float2half_rn(x);
    l = __float2half_rn(x - __half2float(h));
}

// ---------------------------------------------------------------------------
// fp32 -> fp16 (hi, lo) split
// ---------------------------------------------------------------------------
__global__ void __launch_bounds__(256) split_kernel(
    const float* __restrict__ src, f16* __restrict__ hi, f16* __restrict__ lo, int n4)
{
    int i = blockIdx.x * 256 + threadIdx.x;
    if (i >= n4) return;
    float4 v = reinterpret_cast<const float4*>(src)[i];
    f16 h0,h1,h2,h3,l0,l1,l2,l3;
    split1h(v.x,h0,l0); split1h(v.y,h1,l1); split1h(v.z,h2,l2); split1h(v.w,h3,l3);
    f162* H = reinterpret_cast<f162*>(hi);
    f162* L = reinterpret_cast<f162*>(lo);
    H[2*i]   = __halves2half2(h0,h1); H[2*i+1] = __halves2half2(h2,h3);
    L[2*i]   = __halves2half2(l0,l1); L[2*i+1] = __halves2half2(l2,l3);
}

// ---------------------------------------------------------------------------
// V transpose + split: V[b,k,h,d] (fp32) -> Vt[bh][d][k] (fp16 hi/lo)
// ---------------------------------------------------------------------------
__global__ void __launch_bounds__(256) vtrans_kernel(
    const float* __restrict__ V, f16* __restrict__ Vth, f16* __restrict__ Vtl)
{
    __shared__ float t[64][129];
    const int tid = threadIdx.x;
    const int bh = blockIdx.y, b = bh >> 4, h = bh & 15;
    const int k0 = blockIdx.x * 128;
#pragma unroll
    for (int i = 0; i < 32; i++) {
        int idx = tid + i * 256;
        int d = idx & 63, kl = idx >> 6;
        t[d][kl] = V[(size_t)(b * Sq + k0 + kl) * Dm + h * Dhd + d];
    }
    __syncthreads();
#pragma unroll
    for (int i = 0; i < 32; i++) {
        int idx = tid + i * 256;
        int kl = idx & 127, d = idx >> 7;
        f16 hh, ll; split1h(t[d][kl], hh, ll);
        size_t o = ((size_t)bh * 64 + d) * Sq + k0 + kl;
        Vth[o] = hh; Vtl[o] = ll;
    }
}

// ---------------------------------------------------------------------------
// Dense NT GEMM (mma.sync fp16): C = A * B^T, A from hi(+lo), B from hi+lo.
// NA=2: 3 products (fp32-grade). NA=1: 2 products (~1.4e-4 rel).
// Block 128x128, 8 warps (4m x 2n), warp tile 32x64, K-stage 32, 3-stage pipe.
// Outputs: optional fp32 Cf, optional fp16 Ch (+Cl).
// ---------------------------------------------------------------------------
#define DPAD 80            // bytes per smem row (40 f16)
#define DMAT 10240         // bytes per 128x32 matrix

template<int NA>
__global__ void __launch_bounds__(256, 1) gemm_mma(
    const f16* __restrict__ Ah, const f16* __restrict__ Al,
    const f16* __restrict__ Bh, const f16* __restrict__ Bl,
    const float* __restrict__ bias, int relu,
    float* __restrict__ Cf, f16* __restrict__ Ch, f16* __restrict__ Cl,
    int M, int N, int K)
{
    constexpr int NMAT = NA + 2;
    constexpr int STAGE = NMAT * DMAT;
    extern __shared__ __align__(16) char dsm[];
    const uint32_t s0 = smem_u32(dsm);
    const int tid = threadIdx.x, lane = tid & 31, warp = tid >> 5;
    const int wm = warp & 3, wn = warp >> 2;
    const int m0 = blockIdx.y * 128, n0 = blockIdx.x * 128;

    float acc[2][8][4];
#pragma unroll
    for (int a = 0; a < 2; a++)
#pragma unroll
        for (int b = 0; b < 8; b++)
#pragma unroll
            for (int c = 0; c < 4; c++) acc[a][b][c] = 0.f;

    const f16* srcs[NMAT];
    srcs[0] = Ah + (size_t)m0 * K;
    if (NA == 2) srcs[1] = Al + (size_t)m0 * K;
    srcs[NA]     = Bh + (size_t)n0 * K;
    srcs[NA + 1] = Bl + (size_t)n0 * K;

    auto load_stage = [&](int s, int k0) {
        uint32_t base = s0 + s * STAGE;
        int row0 = tid >> 2, ch = tid & 3;
#pragma unroll
        for (int m = 0; m < NMAT; m++) {
#pragma unroll
            for (int i = 0; i < 2; i++) {
                int row = row0 + i * 64;
                CPA16(base + m * DMAT + row * DPAD + ch * 16,
                      srcs[m] + (size_t)row * K + k0 + ch * 8);
            }
        }
        CPA_COMMIT();
    };

    const int NS = K / 32;
    load_stage(0, 0);
    load_stage(1, 32);
    for (int s = 0; s < NS; s++) {
        if (s + 2 < NS) load_stage((s + 2) % 3, (s + 2) * 32);
        else            CPA_COMMIT();
        CPA_WAIT2();
        __syncthreads();
        uint32_t base = s0 + (s % 3) * STAGE;
#pragma unroll
        for (int ks = 0; ks < 2; ks++) {
            uint32_t a_hi[2][4], a_lo[2][4], b_hi[8][2], b_lo[8][2];
#pragma unroll
            for (int mt = 0; mt < 2; mt++) {
                uint32_t off = (uint32_t)((wm*32 + mt*16 + (lane & 15)) * DPAD
                                          + (ks*16 + (lane >> 4) * 8) * 2);
                ldmx4(a_hi[mt], base + off);
                if (NA == 2) ldmx4(a_lo[mt], base + DMAT + off);
            }
#pragma unroll
            for (int np = 0; np < 4; np++) {
                uint32_t off = (uint32_t)((wn*64 + np*16 + (lane & 7) + ((lane >> 4) & 1) * 8) * DPAD
                                          + (ks*16 + ((lane >> 3) & 1) * 8) * 2);
                uint32_t r[4];
                ldmx4(r, base + NA*DMAT + off);
                b_hi[np*2][0] = r[0]; b_hi[np*2][1] = r[1];
                b_hi[np*2+1][0] = r[2]; b_hi[np*2+1][1] = r[3];
                ldmx4(r, base + (NA+1)*DMAT + off);
                b_lo[np*2][0] = r[0]; b_lo[np*2][1] = r[1];
                b_lo[np*2+1][0] = r[2]; b_lo[np*2+1][1] = r[3];
            }
#pragma unroll
            for (int mt = 0; mt < 2; mt++)
#pragma unroll
                for (int nt = 0; nt < 8; nt++) {
                    mma16816(acc[mt][nt], a_hi[mt], b_hi[nt]);
                    mma16816(acc[mt][nt], a_hi[mt], b_lo[nt]);
                    if (NA == 2) mma16816(acc[mt][nt], a_lo[mt], b_hi[nt]);
                }
        }
        __syncthreads();
    }

#pragma unroll
    for (int mt = 0; mt < 2; mt++) {
        int r0 = m0 + wm*32 + mt*16 + (lane >> 2);
#pragma unroll
        for (int half = 0; half < 2; half++) {
            int row = r0 + half * 8;
#pragma unroll
            for (int nt = 0; nt < 8; nt++) {
                int col = n0 + wn*64 + nt*8 + (lane & 3) * 2;
                float v0 = acc[mt][nt][half*2+0], v1 = acc[mt][nt][half*2+1];
                if (bias) { v0 += bias[col]; v1 += bias[col+1]; }
                if (relu) { v0 = fmaxf(v0, 0.f); v1 = fmaxf(v1, 0.f); }
                if (Cf) {
                    float2 o; o.x = v0; o.y = v1;
                    *(float2*)(Cf + (size_t)row * N + col) = o;
                }
                if (Ch) {
                    f16 h0 = __float2half_rn(v0), h1 = __float2half_rn(v1);
                    *(f162*)(Ch + (size_t)row * N + col) = __halves2half2(h0, h1);
                    if (Cl) {
                        f16 l0 = __float2half_rn(v0 - __half2float(h0));
                        f16 l1 = __float2half_rn(v1 - __half2float(h1));
                        *(f162*)(Cl + (size_t)row * N + col) = __halves2half2(l0, l1);
                    }
                }
            }
        }
    }
}

// ---------------------------------------------------------------------------
// Scores (mma.sync fp16, 3-product): per (b,h), 128q x 128k tile, K=64.
// smem: 4 matrices x (128 rows x 144B stride) = 73728B.
// ---------------------------------------------------------------------------
#define SPAD 144
#define SMAT 18432

__global__ void __launch_bounds__(256, 1) scores_mma(
    const f16* __restrict__ Qh, const f16* __restrict__ Ql,
    const f16* __restrict__ KMh, const f16* __restrict__ KMl,
    const int* __restrict__ mask, float* __restrict__ attn)
{
    extern __shared__ __align__(16) char dsm[];
    const uint32_t s0 = smem_u32(dsm);
    const int tid = threadIdx.x, lane = tid & 31, warp = tid >> 5;
    const int wm = warp & 3, wn = warp >> 2;
    const int bh = blockIdx.z, b = bh >> 4, h = bh & 15;
    const int q0 = blockIdx.y * 128, n0 = blockIdx.x * 128;

    const f16* srcs[4] = {
        Qh  + (size_t)(b * Sq + q0) * Dm + h * Dhd,
        Ql  + (size_t)(b * Sq + q0) * Dm + h * Dhd,
        KMh + (size_t)(b * Sq + n0) * Dm + h * Dhd,
        KMl + (size_t)(b * Sq + n0) * Dm + h * Dhd };

#pragma unroll
    for (int m = 0; m < 4; m++) {
#pragma unroll
        for (int i = 0; i < 4; i++) {
            int slot = tid + i * 256;
            int row = slot >> 3, ch = slot & 7;
            *(uint4*)(dsm + m * SMAT + row * SPAD + ch * 16) =
                *(const uint4*)(srcs[m] + (size_t)row * Dm + ch * 8);
        }
    }
    __syncthreads();

    float acc[2][8][4];
#pragma unroll
    for (int a = 0; a < 2; a++)
#pragma unroll
        for (int bb = 0; bb < 8; bb++)
#pragma unroll
            for (int c = 0; c < 4; c++) acc[a][bb][c] = 0.f;

#pragma unroll
    for (int ks = 0; ks < 4; ks++) {
        uint32_t a_hi[2][4], a_lo[2][4], b_hi[8][2], b_lo[8][2];
#pragma unroll
        for (int mt = 0; mt < 2; mt++) {
            uint32_t off = (uint32_t)((wm*32 + mt*16 + (lane & 15)) * SPAD
                                      + (ks*16 + (lane >> 4) * 8) * 2);
            ldmx4(a_hi[mt], s0 + off);
            ldmx4(a_lo[mt], s0 + SMAT + off);
        }
#pragma unroll
        for (int np = 0; np < 4; np++) {
            uint32_t off = (uint32_t)((wn*64 + np*16 + (lane & 7) + ((lane >> 4) & 1) * 8) * SPAD
                                      + (ks*16 + ((lane >> 3) & 1) * 8) * 2);
            uint32_t r[4];
            ldmx4(r, s0 + 2*SMAT + off);
            b_hi[np*2][0] = r[0]; b_hi[np*2][1] = r[1];
            b_hi[np*2+1][0] = r[2]; b_hi[np*2+1][1] = r[3];
            ldmx4(r, s0 + 3*SMAT + off);
            b_lo[np*2][0] = r[0]; b_lo[np*2][1] = r[1];
            b_lo[np*2+1][0] = r[2]; b_lo[np*2+1][1] = r[3];
        }
#pragma unroll
        for (int mt = 0; mt < 2; mt++)
#pragma unroll
            for (int nt = 0; nt < 8; nt++) {
                mma16816(acc[mt][nt], a_hi[mt], b_hi[nt]);
                mma16816(acc[mt][nt], a_hi[mt], b_lo[nt]);
                mma16816(acc[mt][nt], a_lo[mt], b_hi[nt]);
            }
    }

#pragma unroll
    for (int mt = 0; mt < 2; mt++) {
        int r0 = q0 + wm*32 + mt*16 + (lane >> 2);
#pragma unroll
        for (int half = 0; half < 2; half++) {
            int row = r0 + half * 8;
            float* ar = attn + ((size_t)bh * Sq + row) * Sq;
#pragma unroll
            for (int nt = 0; nt < 8; nt++) {
                int col = n0 + wn*64 + nt*8 + (lane & 3) * 2;
                float v0 = acc[mt][nt][half*2+0], v1 = acc[mt][nt][half*2+1];
                v0 = mask[b*Sq + col]     ? -1.25e11f : v0 * 0.125f;
                v1 = mask[b*Sq + col + 1] ? -1.25e11f : v1 * 0.125f;
                float2 o; o.x = v0; o.y = v1;
                *(float2*)(ar + col) = o;
            }
        }
    }
}

// ---------------------------------------------------------------------------
// AV (mma.sync fp16, 2-product): per (b,h), 128q x 64d, K=1024, 3-stage pipe.
// A = Ph only; B = Vt hi/lo. Epilogue emits fp16 avh directly.
// stage: P 10240 + Vth 5120 + Vtl 5120 = 20480B.
// ---------------------------------------------------------------------------
#define AVSTAGE 20480

__global__ void __launch_bounds__(256, 1) av_mma(
    const f16* __restrict__ Ph,
    const f16* __restrict__ Vth, const f16* __restrict__ Vtl,
    f16* __restrict__ avh)
{
    extern __shared__ __align__(16) char dsm[];
    const uint32_t s0 = smem_u32(dsm);
    const int tid = threadIdx.x, lane = tid & 31, warp = tid >> 5;
    const int wm = warp & 3, wn = warp >> 2;
    const int bh = blockIdx.y, b = bh >> 4, h = bh & 15;
    const int q0 = blockIdx.x * 128;
    const f16* pa = Ph + (size_t)bh * Sq * Sq + (size_t)q0 * Sq;
    const f16* pbh = Vth + (size_t)bh * 64 * Sq;
    const f16* pbl = Vtl + (size_t)bh * 64 * Sq;

    float acc[2][4][4];
#pragma unroll
    for (int a = 0; a < 2; a++)
#pragma unroll
        for (int bb = 0; bb < 4; bb++)
#pragma unroll
            for (int c = 0; c < 4; c++) acc[a][bb][c] = 0.f;

    auto load_stage = [&](int s, int k0) {
        uint32_t base = s0 + s * AVSTAGE;
        int row0 = tid >> 2, ch = tid & 3;
#pragma unroll
        for (int i = 0; i < 2; i++) {
            int row = row0 + i * 64;
            CPA16(base + row * DPAD + ch * 16, pa + (size_t)row * Sq + k0 + ch * 8);
        }
        CPA16(base + DMAT + row0 * DPAD + ch * 16,        pbh + (size_t)row0 * Sq + k0 + ch * 8);
        CPA16(base + DMAT + 5120 + row0 * DPAD + ch * 16, pbl + (size_t)row0 * Sq + k0 + ch * 8);
        CPA_COMMIT();
    };

    const int NS = Sq / 32;
    load_stage(0, 0);
    load_stage(1, 32);
    for (int s = 0; s < NS; s++) {
        if (s + 2 < NS) load_stage((s + 2) % 3, (s + 2) * 32);
        else            CPA_COMMIT();
        CPA_WAIT2();
        __syncthreads();
        uint32_t base = s0 + (s % 3) * AVSTAGE;
#pragma unroll
        for (int ks = 0; ks < 2; ks++) {
            uint32_t a_hi[2][4], b_hi[4][2], b_lo[4][2];
#pragma unroll
            for (int mt = 0; mt < 2; mt++) {
                uint32_t off = (uint32_t)((wm*32 + mt*16 + (lane & 15)) * DPAD
                                          + (ks*16 + (lane >> 4) * 8) * 2);
                ldmx4(a_hi[mt], base + off);
            }
#pragma unroll
            for (int np = 0; np < 2; np++) {
                uint32_t off = (uint32_t)((wn*32 + np*16 + (lane & 7) + ((lane >> 4) & 1) * 8) * DPAD
                                          + (ks*16 + ((lane >> 3) & 1) * 8) * 2);
                uint32_t r[4];
                ldmx4(r, base + DMAT + off);
                b_hi[np*2][0] = r[0]; b_hi[np*2][1] = r[1];
                b_hi[np*2+1][0] = r[2]; b_hi[np*2+1][1] = r[3];
                ldmx4(r, base + DMAT + 5120 + off);
                b_lo[np*2][0] = r[0]; b_lo[np*2][1] = r[1];
                b_lo[np*2+1][0] = r[2]; b_lo[np*2+1][1] = r[3];
            }
#pragma unroll
            for (int mt = 0; mt < 2; mt++)
#pragma unroll
                for (int nt = 0; nt < 4; nt++) {
                    mma16816(acc[mt][nt], a_hi[mt], b_hi[nt]);
                    mma16816(acc[mt][nt], a_hi[mt], b_lo[nt]);
                }
        }
        __syncthreads();
    }

#pragma unroll
    for (int mt = 0; mt < 2; mt++) {
        int r0 = q0 + wm*32 + mt*16 + (lane >> 2);
#pragma unroll
        for (int half = 0; half < 2; half++) {
            int row = r0 + half * 8;
            f16* orow = avh + (size_t)(b * Sq + row) * Dm + h * Dhd;
#pragma unroll
            for (int nt = 0; nt < 4; nt++) {
                int col = wn*32 + nt*8 + (lane & 3) * 2;
                *(f162*)(orow + col) = __floats2half2_rn(acc[mt][nt][half*2+0],
                                                         acc[mt][nt][half*2+1]);
            }
        }
    }
}

// ---------------------------------------------------------------------------
// Row softmax in place + fp16 P (hi only). One block per row.
// ---------------------------------------------------------------------------
__global__ void __launch_bounds__(256) softmax_split_kernel(
    float* __restrict__ attn, f16* __restrict__ Ph)
{
    __shared__ float sh[32];
    const size_t rowo = (size_t)blockIdx.x * Sq;
    float* p = attn + rowo;
    const int tid = threadIdx.x;

    float4 v = reinterpret_cast<float4*>(p)[tid];
    float mx = fmaxf(fmaxf(v.x, v.y), fmaxf(v.z, v.w));
#pragma unroll
    for (int o = 16; o; o >>= 1) mx = fmaxf(mx, __shfl_xor_sync(0xffffffffu, mx, o));
    if ((tid & 31) == 0) sh[tid >> 5] = mx;
    __syncthreads();
    if (tid < 32) {
        float m = (tid < 8) ? sh[tid] : -INFINITY;
#pragma unroll
        for (int o = 4; o; o >>= 1) m = fmaxf(m, __shfl_xor_sync(0xffffffffu, m, o));
        if (tid == 0) sh[0] = m;
    }
    __syncthreads();
    mx = sh[0];
    __syncthreads();

    v.x = __expf(v.x - mx); v.y = __expf(v.y - mx);
    v.z = __expf(v.z - mx); v.w = __expf(v.w - mx);
    float s = v.x + v.y + v.z + v.w;
#pragma unroll
    for (int o = 16; o; o >>= 1) s += __shfl_xor_sync(0xffffffffu, s, o);
    if ((tid & 31) == 0) sh[tid >> 5] = s;
    __syncthreads();
    if (tid < 32) {
        float m = (tid < 8) ? sh[tid] : 0.f;
#pragma unroll
        for (int o = 4; o; o >>= 1) m += __shfl_xor_sync(0xffffffffu, m, o);
        if (tid == 0) sh[0] = m;
    }
    __syncthreads();
    float inv = 1.f / sh[0];
    v.x *= inv; v.y *= inv; v.z *= inv; v.w *= inv;
    reinterpret_cast<float4*>(p)[tid] = v;

    f162* H = reinterpret_cast<f162*>(Ph + rowo);
    H[2*tid]   = __floats2half2_rn(v.x, v.y);
    H[2*tid+1] = __floats2half2_rn(v.z, v.w);
}

// ---------------------------------------------------------------------------
// LayerNorm(a + r), torch semantics (ddof=1, eps on std); optional fp16 hi out.
// ---------------------------------------------------------------------------
__global__ void __launch_bounds__(256) ln_kernel(
    const float* __restrict__ a, const float* __restrict__ r,
    const float* __restrict__ gamma, const float* __restrict__ beta,
    float* __restrict__ y, f16* __restrict__ yh)
{
    __shared__ float sh[32];
    const int row = blockIdx.x;
    const int tid = threadIdx.x;

    float4 v = reinterpret_cast<const float4*>(a + (size_t)row * Dm)[tid];
    float4 vr = reinterpret_cast<const float4*>(r + (size_t)row * Dm)[tid];
    v.x += vr.x; v.y += vr.y; v.z += vr.z; v.w += vr.w;

    float s = v.x + v.y + v.z + v.w;
#pragma unroll
    for (int o = 16; o; o >>= 1) s += __shfl_xor_sync(0xffffffffu, s, o);
    if ((tid & 31) == 0) sh[tid >> 5] = s;
    __syncthreads();
    if (tid < 32) {
        float m = (tid < 8) ? sh[tid] : 0.f;
#pragma unroll
        for (int o = 4; o; o >>= 1) m += __shfl_xor_sync(0xffffffffu, m, o);
        if (tid == 0) sh[0] = m;
    }
    __syncthreads();
    float mean = sh[0] * (1.0f / Dm);
    __syncthreads();

    float dx = v.x - mean, dy = v.y - mean, dz = v.z - mean, dw = v.w - mean;
    float s2 = dx*dx + dy*dy + dz*dz + dw*dw;
#pragma unroll
    for (int o = 16; o; o >>= 1) s2 += __shfl_xor_sync(0xffffffffu, s2, o);
    if ((tid & 31) == 0) sh[tid >> 5] = s2;
    __syncthreads();
    if (tid < 32) {
        float m = (tid < 8) ? sh[tid] : 0.f;
#pragma unroll
        for (int o = 4; o; o >>= 1) m += __shfl_xor_sync(0xffffffffu, m, o);
        if (tid == 0) sh[0] = m;
    }
    __syncthreads();
    float var = sh[0] * (1.0f / (Dm - 1));
    float inv = 1.0f / (sqrtf(var) + 1e-8f);

    float4 g = reinterpret_cast<const float4*>(gamma)[tid];
    float4 bb = reinterpret_cast<const float4*>(beta)[tid];
    float4 o;
    o.x = g.x * dx * inv + bb.x;
    o.y = g.y * dy * inv + bb.y;
    o.z = g.z * dz * inv + bb.z;
    o.w = g.w * dw * inv + bb.w;
    reinterpret_cast<float4*>(y + (size_t)row * Dm)[tid] = o;

    if (yh) {
        f162* H = reinterpret_cast<f162*>(yh + (size_t)row * Dm);
        H[2*tid]   = __floats2half2_rn(o.x, o.y);
        H[2*tid+1] = __floats2half2_rn(o.z, o.w);
    }
}

// ---------------------------------------------------------------------------
// Launch
// ---------------------------------------------------------------------------
extern "C" void kernel_launch(void* const* d_in, const int* in_sizes, int n_in,
                              void* d_out, int out_size)
{
    const float* x      = (const float*)d_in[0];
    const int*   mask   = (const int*)  d_in[1];
    const float* W[6]   = { (const float*)d_in[2], (const float*)d_in[3],
                            (const float*)d_in[4], (const float*)d_in[5],
                            (const float*)d_in[6], (const float*)d_in[8] };
    const float* b1     = (const float*)d_in[7];
    const float* b2     = (const float*)d_in[9];
    const float* gamma1 = (const float*)d_in[10];
    const float* beta1  = (const float*)d_in[11];
    const float* gamma2 = (const float*)d_in[12];
    const float* beta2  = (const float*)d_in[13];
    float* out = (float*)d_out;

    float *pV,*px1,*pff,*pattn_fb;
    cudaGetSymbolAddress((void**)&pV, g_V);
    cudaGetSymbolAddress((void**)&px1, g_x1);
    cudaGetSymbolAddress((void**)&pff, g_ff);
    cudaGetSymbolAddress((void**)&pattn_fb, g_attn_fb);
    f16 *pxh,*pxl,*pQh,*pQl,*pKh,*pKl,*pavh,*px1h,*ph1h,*pWh,*pWl,*pVth,*pVtl,*pPh;
    cudaGetSymbolAddress((void**)&pxh, g_xh);   cudaGetSymbolAddress((void**)&pxl, g_xl);
    cudaGetSymbolAddress((void**)&pQh, g_Qh);   cudaGetSymbolAddress((void**)&pQl, g_Ql);
    cudaGetSymbolAddress((void**)&pKh, g_Kh);   cudaGetSymbolAddress((void**)&pKl, g_Kl);
    cudaGetSymbolAddress((void**)&pavh, g_avh);
    cudaGetSymbolAddress((void**)&px1h, g_x1h);
    cudaGetSymbolAddress((void**)&ph1h, g_h1h);
    cudaGetSymbolAddress((void**)&pWh, g_Wh);   cudaGetSymbolAddress((void**)&pWl, g_Wl);
    cudaGetSymbolAddress((void**)&pVth, g_Vth); cudaGetSymbolAddress((void**)&pVtl, g_Vtl);
    cudaGetSymbolAddress((void**)&pPh, g_Ph);

    float* attn = ((size_t)out_size >= OUT_ELEMS + ATTN_ELEMS) ? (out + OUT_ELEMS) : pattn_fb;

    const int GM2_SMEM = 3 * 4 * DMAT;     // 122880
    const int GM1_SMEM = 3 * 3 * DMAT;     // 92160
    const int SC_SMEM  = 4 * SMAT;         // 73728
    const int AV_SMEM  = 3 * AVSTAGE;      // 61440
    cudaFuncSetAttribute(gemm_mma<2>, cudaFuncAttributeMaxDynamicSharedMemorySize, GM2_SMEM);
    cudaFuncSetAttribute(gemm_mma<1>, cudaFuncAttributeMaxDynamicSharedMemorySize, GM1_SMEM);
    cudaFuncSetAttribute(scores_mma,  cudaFuncAttributeMaxDynamicSharedMemorySize, SC_SMEM);
    cudaFuncSetAttribute(av_mma,      cudaFuncAttributeMaxDynamicSharedMemorySize, AV_SMEM);

    dim3 blk(256);
    const int N4x = (Mrows * Dm) / 4;
    const int N4w = (Dm * Dm) / 4;
    dim3 gGemm(Dm / 128, Mrows / 128);     // (8, 16)
    const size_t WS = (size_t)Dm * Dm;

    // Splits: x + 6 weights (hi/lo)
    split_kernel<<<N4x / 256, blk>>>(x, pxh, pxl, N4x);
    for (int w = 0; w < 6; w++)
        split_kernel<<<N4w / 256, blk>>>(W[w], pWh + w * WS, pWl + w * WS, N4w);

    // QKV projections (3-product). Q,K -> fp16 hi/lo; V -> fp32.
    gemm_mma<2><<<gGemm, blk, GM2_SMEM>>>(pxh, pxl, pWh + 0*WS, pWl + 0*WS,
        nullptr, 0, nullptr, pQh, pQl, Mrows, Dm, Dm);
    gemm_mma<2><<<gGemm, blk, GM2_SMEM>>>(pxh, pxl, pWh + 1*WS, pWl + 1*WS,
        nullptr, 0, nullptr, pKh, pKl, Mrows, Dm, Dm);
    gemm_mma<2><<<gGemm, blk, GM2_SMEM>>>(pxh, pxl, pWh + 2*WS, pWl + 2*WS,
        nullptr, 0, pV, nullptr, nullptr, Mrows, Dm, Dm);

    vtrans_kernel<<<dim3(Sq / 128, 32), blk>>>(pV, pVth, pVtl);

    // Attention logits (masked+scaled) -> attn
    scores_mma<<<dim3(Sq / 128, Sq / 128, Bsz * Hn), blk, SC_SMEM>>>(pQh, pQl, pKh, pKl, mask, attn);

    // Softmax in place + P fp16 (hi only)
    softmax_split_kernel<<<(unsigned)(Bsz * Hn * Sq), blk>>>(attn, pPh);

    // attn @ V (2-product) -> avh fp16
    av_mma<<<dim3(Sq / 128, Bsz * Hn), blk, AV_SMEM>>>(pPh, pVth, pVtl, pavh);

    // Output projection (2-product) -> fp32, then LN1 (+x1h fp16)
    gemm_mma<1><<<gGemm, blk, GM1_SMEM>>>(pavh, nullptr, pWh + 3*WS, pWl + 3*WS,
        nullptr, 0, pff, nullptr, nullptr, Mrows, Dm, Dm);
    ln_kernel<<<Mrows, blk>>>(x, pff, gamma1, beta1, px1, px1h);

    // FFN: W1 (bias+relu) -> h1h fp16 only; W2 (bias) -> fp32 ff
    gemm_mma<1><<<gGemm, blk, GM1_SMEM>>>(px1h, nullptr, pWh + 4*WS, pWl + 4*WS,
        b1, 1, nullptr, ph1h, nullptr, Mrows, Dm, Dm);
    gemm_mma<1><<<gGemm, blk, GM1_SMEM>>>(ph1h, nullptr, pWh + 5*WS, pWl + 5*WS,
        b2, 0, pff, nullptr, nullptr, Mrows, Dm, Dm);

    // LN2 -> out
    ln_kernel<<<Mrows, blk>>>(px1, pff, gamma2, beta2, out, nullptr);
}